// round 1
// baseline (speedup 1.0000x reference)
#include <cuda_runtime.h>
#include <math.h>

// Shapes fixed by the problem instance
#define KB    4
#define CIN   8
#define COUT  64
#define NLEN  4096

// Scratch for the 32 complex DFT-bin sums Z[k, ci]
__device__ float g_Zr[KB * CIN];
__device__ float g_Zi[KB * CIN];

// Kernel 1: Z[k,ci] = sum_s (zr + i*zi)[k,ci,s] * e^{+i*omega*s}
__global__ __launch_bounds__(256) void zred_kernel(
    const float* __restrict__ zr, const float* __restrict__ zi,
    const int* __restrict__ mptr)
{
    const int b = blockIdx.x;              // b = k*CIN + ci
    const float* r  = zr + (size_t)b * NLEN;
    const float* im = zi + (size_t)b * NLEN;
    const int   m     = *mptr;
    const float omega = (float)(6.283185307179586 * (double)m / (double)NLEN);

    float ar = 0.f, ai = 0.f;
    for (int t = threadIdx.x; t < NLEN; t += 256) {
        float s, c;
        sincosf(omega * (float)t, &s, &c);
        float x = r[t], y = im[t];
        ar += x * c - y * s;
        ai += x * s + y * c;
    }

    __shared__ float shr[256], shi[256];
    shr[threadIdx.x] = ar;
    shi[threadIdx.x] = ai;
    __syncthreads();
    for (int off = 128; off > 0; off >>= 1) {
        if (threadIdx.x < off) {
            shr[threadIdx.x] += shr[threadIdx.x + off];
            shi[threadIdx.x] += shi[threadIdx.x + off];
        }
        __syncthreads();
    }
    if (threadIdx.x == 0) {
        g_Zr[b] = shr[0];
        g_Zi[b] = shi[0];
    }
}

// Kernel 2: per (k,co) build G = sum_ci |A| e^{i beta} Z[k,ci], gate scalar,
// then stream out[mu] = gate * e^{-i omega mu} * G  (real half, imag half).
__global__ __launch_bounds__(256) void out_kernel(
    const float* __restrict__ A, const float* __restrict__ beta,
    const float* __restrict__ bias, const int* __restrict__ mptr,
    float* __restrict__ out)
{
    const int b  = blockIdx.x;             // b = k*COUT + co
    const int k  = b >> 6;
    const int co = b & 63;
    const int   m     = *mptr;
    const float omega = (float)(6.283185307179586 * (double)m / (double)NLEN);

    float Gr = 0.f, Gi = 0.f;
#pragma unroll
    for (int ci = 0; ci < CIN; ci++) {
        float a = fabsf(A[co * CIN + ci]);
        float sb, cb;
        sincosf(beta[co * CIN + ci], &sb, &cb);
        float Wr = a * cb, Wi = a * sb;
        float Zr = g_Zr[k * CIN + ci];
        float Zi = g_Zi[k * CIN + ci];
        Gr += Wr * Zr - Wi * Zi;
        Gi += Wr * Zi + Wi * Zr;
    }
    float mag  = sqrtf(Gr * Gr + Gi * Gi);
    float gate = (1.f / (1.f + expf(-(mag + bias[co])))) / (mag + 1e-5f);
    float gr = gate * Gr, gi = gate * Gi;

    float* outr = out + (size_t)b * NLEN;
    float* outi = out + (size_t)KB * COUT * NLEN + (size_t)b * NLEN;

    // grid.y tiles of 1024 mu; each thread writes one float4 per half
    const int mu0 = blockIdx.y * 1024 + threadIdx.x * 4;
    float4 vr, vi;
    float cs[4], sn[4];
#pragma unroll
    for (int j = 0; j < 4; j++)
        sincosf(omega * (float)(mu0 + j), &sn[j], &cs[j]);

    // S = e^{-i omega mu} * G = (Gr*c + Gi*s) + i*(Gi*c - Gr*s)
    vr.x = gr * cs[0] + gi * sn[0];  vi.x = gi * cs[0] - gr * sn[0];
    vr.y = gr * cs[1] + gi * sn[1];  vi.y = gi * cs[1] - gr * sn[1];
    vr.z = gr * cs[2] + gi * sn[2];  vi.z = gi * cs[2] - gr * sn[2];
    vr.w = gr * cs[3] + gi * sn[3];  vi.w = gi * cs[3] - gr * sn[3];

    *reinterpret_cast<float4*>(outr + mu0) = vr;
    *reinterpret_cast<float4*>(outi + mu0) = vi;
}

extern "C" void kernel_launch(void* const* d_in, const int* in_sizes, int n_in,
                              void* d_out, int out_size)
{
    const float* z_real = (const float*)d_in[0];
    const float* z_imag = (const float*)d_in[1];
    const float* A      = (const float*)d_in[2];
    const float* beta   = (const float*)d_in[3];
    const float* bias   = (const float*)d_in[4];
    const int*   mptr   = (const int*)d_in[5];
    float* out = (float*)d_out;

    zred_kernel<<<KB * CIN, 256>>>(z_real, z_imag, mptr);

    dim3 grid(KB * COUT, NLEN / 1024);
    out_kernel<<<grid, 256>>>(A, beta, bias, mptr, out);
}